// round 4
// baseline (speedup 1.0000x reference)
#include <cuda_runtime.h>
#include <math.h>

// B=4096 samples, M=4 modes, L=4 layers, D=8 cutoff. state idx = i0*512+i1*64+i2*8+i3.
#define BSROW 66
#define BSSZ  (64 * BSROW)           // 4224 float2 per BS gate (transposed [k][i])

__device__ float4 g_bs[48 * (BSSZ / 2)];   // 48 BS gates
__device__ float2 g_sq[16 * 64];           // [L][M] squeeze' (intf2 rot folded)
__device__ float2 g_dp[16 * 64];           // [L][M] disp' (Kerr + next intf1 rot folded)
__device__ float2 g_enc[4096 * 4 * 8];     // [B][M][8] encoding col-0 (rot1 l=0 folded)

__device__ __forceinline__ float2 cmul(float2 a, float2 b) {
    return make_float2(a.x * b.x - a.y * b.y, a.x * b.y + a.y * b.x);
}

// ---------------------------------------------------------------------------
// Block-cooperative expm: scaling-and-squaring + Taylor-12 (scaled norm <= 1).
// H,P,E,T: n*n complex SMEM buffers. Returns pointer to result buffer.
// ---------------------------------------------------------------------------
__device__ float2* block_expm(float2* H, float2* P, float2* E, float2* T,
                              float* red, int* s_sh, int n, int ln) {
    const int tid = threadIdx.x, nt = blockDim.x, N2 = n * n;
    if (tid < n) {
        float s = 0.f;
        for (int c = 0; c < n; c++) { float2 h = H[(tid << ln) + c]; s += fabsf(h.x) + fabsf(h.y); }
        red[tid] = s;
    }
    __syncthreads();
    if (tid == 0) {
        float m = 0.f;
        for (int r = 0; r < n; r++) m = fmaxf(m, red[r]);
        int s = 0;
        while (m > 1.0f && s < 48) { m *= 0.5f; s++; }
        *s_sh = s;
    }
    __syncthreads();
    const int s = *s_sh;
    const float scale = ldexpf(1.0f, -s);
    for (int e = tid; e < N2; e += nt) { float2 h = H[e]; h.x *= scale; h.y *= scale; H[e] = h; }
    __syncthreads();
    for (int e = tid; e < N2; e += nt) {
        float2 h = H[e];
        P[e] = h;
        if ((e >> ln) == (e & (n - 1))) h.x += 1.0f;
        E[e] = h;
    }
    __syncthreads();
    for (int k = 2; k <= 12; k++) {
        const float inv = 1.0f / (float)k;
        for (int e = tid; e < N2; e += nt) {
            int r = e >> ln, c = e & (n - 1);
            float2 acc = make_float2(0.f, 0.f);
            for (int m = 0; m < n; m++) {
                float2 a = P[(r << ln) + m], b = H[(m << ln) + c];
                acc.x += a.x * b.x - a.y * b.y;
                acc.y += a.x * b.y + a.y * b.x;
            }
            acc.x *= inv; acc.y *= inv;
            T[e] = acc;
        }
        __syncthreads();
        for (int e = tid; e < N2; e += nt) { E[e].x += T[e].x; E[e].y += T[e].y; }
        { float2* tmp = P; P = T; T = tmp; }
        __syncthreads();
    }
    for (int q = 0; q < s; q++) {
        for (int e = tid; e < N2; e += nt) {
            int r = e >> ln, c = e & (n - 1);
            float2 acc = make_float2(0.f, 0.f);
            for (int m = 0; m < n; m++) {
                float2 a = E[(r << ln) + m], b = E[(m << ln) + c];
                acc.x += a.x * b.x - a.y * b.y;
                acc.y += a.x * b.y + a.y * b.x;
            }
            T[e] = acc;
        }
        __syncthreads();
        { float2* tmp = E; E = T; T = tmp; }
        __syncthreads();
    }
    return E;
}

// ---------------------------------------------------------------------------
// Shared gate precompute: 48 BS (64x64) + 16 squeeze + 16 displacement (8x8).
// ---------------------------------------------------------------------------
extern __shared__ float2 dynbuf[];

__global__ void __launch_bounds__(256) precomp_gates(
        const float* __restrict__ th1, const float* __restrict__ ph1,
        const float* __restrict__ th2, const float* __restrict__ ph2,
        const float* __restrict__ dr,  const float* __restrict__ dphi,
        const float* __restrict__ sr,  const float* __restrict__ sphi,
        const float* __restrict__ kp) {
    float2* H = dynbuf;
    float2* P = dynbuf + 4096;
    float2* E = dynbuf + 8192;
    float2* T = dynbuf + 12288;
    float*  red = (float*)(dynbuf + 16384);
    __shared__ int s_sh;
    const int bid = blockIdx.x, tid = threadIdx.x;

    if (bid < 48) {
        const int l = bid / 12, t = (bid / 6) % 2, p = bid % 6;
        const int PI6[6] = {0, 0, 0, 1, 1, 2}, PJ6[6] = {1, 2, 3, 2, 3, 3};
        const int i = PI6[p], j = PJ6[p];
        const float* TH = t ? th2 : th1;
        const float* PH = t ? ph2 : ph1;
        const float theta = TH[l * 16 + i * 4 + j];
        const float phi   = PH[l * 16 + i * 4 + j];
        const float post  = PH[l * 16 + j * 4 + i];   // rotation on mode j after BS
        float sp, cp;
        sincosf(phi, &sp, &cp);
        // H[(a,b),(c,d)] = th*( e^{i phi} sqrt(c)sqrt(b) [a=c-1][d=b-1]
        //                     - e^{-i phi} sqrt(a)sqrt(d) [c=a-1][b=d-1] )
        for (int e = tid; e < 4096; e += 256) {
            int R = e >> 6, C = e & 63;
            int a = R >> 3, b = R & 7, c = C >> 3, d = C & 7;
            float2 h = make_float2(0.f, 0.f);
            if (a == c - 1 && d == b - 1) {
                float co = theta * sqrtf((float)(c * b));
                h.x += co * cp; h.y += co * sp;
            }
            if (c == a - 1 && b == d - 1) {
                float co = theta * sqrtf((float)(a * d));
                h.x -= co * cp; h.y += co * sp;
            }
            H[e] = h;
        }
        __syncthreads();
        float2* R2 = block_expm(H, P, E, T, red, &s_sh, 64, 6);
        // store transposed [K][I] with row phase e^{i post*(I&7)} folded
        float2* out = (float2*)g_bs + (size_t)bid * BSSZ;
        for (int e = tid; e < 4096; e += 256) {
            int I = e >> 6, K = e & 63;
            float si, co;
            sincosf(post * (float)(I & 7), &si, &co);
            float2 v = R2[e];
            out[K * BSROW + I] = make_float2(v.x * co - v.y * si, v.x * si + v.y * co);
        }
    } else {
        int g = bid - 48;
        const bool isSQ = (g < 16);
        if (!isSQ) g -= 16;
        const int l = g >> 2, w = g & 3;
        if (tid < 64) {
            int i = tid >> 3, k = tid & 7;
            float2 h = make_float2(0.f, 0.f);
            if (isSQ) {
                float r = sr[l * 4 + w], ph = sphi[l * 4 + w];
                float zr = r * cosf(ph), zi = r * sinf(ph);
                if (k == i + 2) {       // 0.5*conj(z)*A^2
                    float co = 0.5f * sqrtf((float)((i + 1) * (i + 2)));
                    h.x += co * zr; h.y -= co * zi;
                }
                if (i == k + 2) {       // -0.5*z*Ad^2
                    float co = 0.5f * sqrtf((float)((k + 1) * (k + 2)));
                    h.x -= co * zr; h.y -= co * zi;
                }
            } else {
                float r = dr[l * 4 + w], ph = dphi[l * 4 + w];
                float amp = r * cosf(ph), ang = r * sinf(ph);
                float ar = amp * cosf(ang), ai = amp * sinf(ang);
                if (k == i - 1) { float co = sqrtf((float)i); h.x += co * ar; h.y += co * ai; }
                if (i == k - 1) { float co = sqrtf((float)k); h.x -= co * ar; h.y += co * ai; }
            }
            H[tid] = h;
        }
        __syncthreads();
        float2* R2 = block_expm(H, P, E, T, red, &s_sh, 8, 3);
        if (tid < 64) {
            int i = tid >> 3;
            float ang;
            if (isSQ) {
                ang = ph2[l * 16 + w * 4 + w] * (float)i;          // intf2 pre-rot
            } else {
                ang = kp[l * 4 + w] * (float)(i * i);              // Kerr
                if (l < 3) ang += ph1[(l + 1) * 16 + w * 4 + w] * (float)i;
            }
            float si, co;
            sincosf(ang, &si, &co);
            float2 v = R2[tid];
            (isSQ ? g_sq : g_dp)[g * 64 + tid] =
                make_float2(v.x * co - v.y * si, v.x * si + v.y * co);
        }
    }
}

// ---------------------------------------------------------------------------
// Per-sample encoding: col 0 of expm(x(Ad - A)), layer-0 rot1 folded in.
// ---------------------------------------------------------------------------
__global__ void __launch_bounds__(64) precomp_enc(const float* __restrict__ x,
                                                  const float* __restrict__ ph1) {
    __shared__ float2 H[64], P[64], E[64], T[64];
    __shared__ float red[8];
    __shared__ int s_sh;
    const int bm = blockIdx.x, m = bm & 3, tid = threadIdx.x;
    const float xv = x[bm];   // x is [B,4] row-major; bm = b*4+m
    if (tid < 64) {
        int i = tid >> 3, k = tid & 7;
        float h = 0.f;
        if (k == i - 1) h += xv * sqrtf((float)i);
        if (i == k - 1) h -= xv * sqrtf((float)k);
        H[tid] = make_float2(h, 0.f);
    }
    __syncthreads();
    float2* R = block_expm(H, P, E, T, red, &s_sh, 8, 3);
    if (tid < 8) {
        float ang = ph1[m * 4 + m] * (float)tid;    // layer 0: ph1[0][m][m]
        float si, co;
        sincosf(ang, &si, &co);
        float2 v = R[tid * 8];                      // column 0
        g_enc[bm * 8 + tid] = make_float2(v.x * co - v.y * si, v.x * si + v.y * co);
    }
}

// ---------------------------------------------------------------------------
// Main simulation: 1 CTA per sample, state in SMEM ping-pong.
// ---------------------------------------------------------------------------
template<int S1, int S2, int SA, int SB>
__device__ __forceinline__ void applyBS(const float2* __restrict__ gate,
                                        const float2* __restrict__ in,
                                        float2* __restrict__ out, int tid) {
    const int ij = tid & 63, og = tid >> 6;
    const float2* g = gate + ij;
    const float2* base = in + og * 2 * SA;
    float2 acc[16];
#pragma unroll
    for (int r = 0; r < 16; r++) acc[r] = make_float2(0.f, 0.f);
#pragma unroll 8
    for (int kl = 0; kl < 64; kl++) {
        float2 u = g[kl * BSROW];
        const float2* p = base + (kl >> 3) * S1 + (kl & 7) * S2;
#pragma unroll
        for (int r = 0; r < 16; r++) {
            float2 s = p[(r >> 3) * SA + (r & 7) * SB];
            acc[r].x = fmaf(u.x, s.x, fmaf(-u.y, s.y, acc[r].x));
            acc[r].y = fmaf(u.x, s.y, fmaf(u.y, s.x, acc[r].y));
        }
    }
    const int ob = (ij >> 3) * S1 + (ij & 7) * S2 + og * 2 * SA;
#pragma unroll
    for (int r = 0; r < 16; r++)
        out[ob + (r >> 3) * SA + (r & 7) * SB] = acc[r];
}

template<int S, int SA, int SB, int SC>
__device__ __forceinline__ void applySingle(const float2* __restrict__ mg,
                                            float2* __restrict__ st, int tid) {
#pragma unroll
    for (int q = 0; q < 2; q++) {
        int f = tid + q * 256;
        int base = (f >> 6) * SA + ((f >> 3) & 7) * SB + (f & 7) * SC;
        float2 v[8];
#pragma unroll
        for (int k = 0; k < 8; k++) v[k] = st[base + k * S];
#pragma unroll
        for (int i = 0; i < 8; i++) {
            float2 a = make_float2(0.f, 0.f);
#pragma unroll
            for (int k = 0; k < 8; k++) {
                float2 u = mg[i * 8 + k];
                a.x = fmaf(u.x, v[k].x, fmaf(-u.y, v[k].y, a.x));
                a.y = fmaf(u.x, v[k].y, fmaf(u.y, v[k].x, a.y));
            }
            st[base + i * S] = a;   // v held in regs: in-place safe
        }
    }
}

__global__ void __launch_bounds__(256, 2) sim_kernel(float* __restrict__ out) {
    float2* sA = dynbuf;
    float2* sB = dynbuf + 4096;
    float2* gbuf = dynbuf + 8192;          // 4224 float2
    __shared__ float2 enc[4][8];
    const int tid = threadIdx.x, b = blockIdx.x;

    if (tid < 32) enc[tid >> 3][tid & 7] = g_enc[b * 32 + tid];
    __syncthreads();
#pragma unroll
    for (int q = 0; q < 16; q++) {
        int idx = tid + q * 256;
        sA[idx] = cmul(cmul(enc[0][idx >> 9], enc[1][(idx >> 6) & 7]),
                       cmul(enc[2][(idx >> 3) & 7], enc[3][idx & 7]));
    }
    float2 *cur = sA, *nxt = sB;

    for (int l = 0; l < 4; l++) {
        for (int t = 0; t < 2; t++) {
            for (int p = 0; p < 6; p++) {
                __syncthreads();
                const float4* src = g_bs + (size_t)(l * 12 + t * 6 + p) * (BSSZ / 2);
                float4* dst = (float4*)gbuf;
                for (int i2 = tid; i2 < BSSZ / 2; i2 += 256) dst[i2] = src[i2];
                __syncthreads();
                switch (p) {
                    case 0: applyBS<512, 64, 8, 1>(gbuf, cur, nxt, tid); break;
                    case 1: applyBS<512, 8, 64, 1>(gbuf, cur, nxt, tid); break;
                    case 2: applyBS<512, 1, 64, 8>(gbuf, cur, nxt, tid); break;
                    case 3: applyBS<64, 8, 512, 1>(gbuf, cur, nxt, tid); break;
                    case 4: applyBS<64, 1, 512, 8>(gbuf, cur, nxt, tid); break;
                    case 5: applyBS<8, 1, 512, 64>(gbuf, cur, nxt, tid); break;
                }
                { float2* tmp = cur; cur = nxt; nxt = tmp; }
            }
            const float2* gptr = (t == 0) ? g_sq : g_dp;
            for (int w = 0; w < 4; w++) {
                __syncthreads();
                if (tid < 64) gbuf[tid] = gptr[(l * 4 + w) * 64 + tid];
                __syncthreads();
                switch (w) {
                    case 0: applySingle<512, 64, 8, 1>(gbuf, cur, tid); break;
                    case 1: applySingle<64, 512, 8, 1>(gbuf, cur, tid); break;
                    case 2: applySingle<8, 512, 64, 1>(gbuf, cur, tid); break;
                    case 3: applySingle<1, 512, 64, 8>(gbuf, cur, tid); break;
                }
            }
        }
    }
    __syncthreads();

    float acc[4] = {0.f, 0.f, 0.f, 0.f};
#pragma unroll
    for (int q = 0; q < 16; q++) {
        int idx = tid + q * 256;
        float2 v = cur[idx];
        float pr = v.x * v.x + v.y * v.y;
        acc[0] += (float)(idx >> 9) * pr;
        acc[1] += (float)((idx >> 6) & 7) * pr;
        acc[2] += (float)((idx >> 3) & 7) * pr;
        acc[3] += (float)(idx & 7) * pr;
    }
    float* red = (float*)nxt;
#pragma unroll
    for (int w = 0; w < 4; w++) red[w * 256 + tid] = acc[w];
    __syncthreads();
    for (int s = 128; s > 0; s >>= 1) {
        if (tid < s) {
#pragma unroll
            for (int w = 0; w < 4; w++) red[w * 256 + tid] += red[w * 256 + tid + s];
        }
        __syncthreads();
    }
    if (tid < 4) out[b * 4 + tid] = red[tid * 256];
}

// ---------------------------------------------------------------------------
extern "C" void kernel_launch(void* const* d_in, const int* in_sizes, int n_in,
                              void* d_out, int out_size) {
    const float* x    = (const float*)d_in[0];
    const float* th1  = (const float*)d_in[1];
    const float* ph1  = (const float*)d_in[2];
    const float* th2  = (const float*)d_in[3];
    const float* ph2  = (const float*)d_in[4];
    const float* dr   = (const float*)d_in[5];
    const float* dphi = (const float*)d_in[6];
    const float* sr   = (const float*)d_in[7];
    const float* sphi = (const float*)d_in[8];
    const float* kp   = (const float*)d_in[9];
    float* out = (float*)d_out;

    const size_t smemG = 16384 * sizeof(float2) + 64 * sizeof(float);   // 131328
    const size_t smemS = (size_t)(4096 * 2 + BSSZ) * sizeof(float2);    //  99328
    cudaFuncSetAttribute(precomp_gates, cudaFuncAttributeMaxDynamicSharedMemorySize, (int)smemG);
    cudaFuncSetAttribute(sim_kernel,    cudaFuncAttributeMaxDynamicSharedMemorySize, (int)smemS);

    precomp_gates<<<80, 256, smemG>>>(th1, ph1, th2, ph2, dr, dphi, sr, sphi, kp);
    precomp_enc<<<16384, 64>>>(x, ph1);
    sim_kernel<<<4096, 256, smemS>>>(out);
}